// round 15
// baseline (speedup 1.0000x reference)
#include <cuda_runtime.h>
#include <cuda_fp16.h>
#include <cstdint>

// R15: fused single-GEMM-per-step. W[416 x 112]: rows 0-207 L2 gates(t),
// rows 208-415 L1 gates(t+1). A[16 x 112] = [h1(t)|x(t+1)|1|h2(t-1)].
// One barrier/step. fp16 3-pass hi/lo (lo x1024). 2 teams x 13 warps.

typedef uint32_t u32;

#define NT 832
#define TLEN 512
#define RS 232
#define W_H 0
#define W_L 96512
#define A_O 193024
#define ATS 3712
#define AT(tm, buf, part) (A_O + (((tm) * 2 + (buf)) * 2 + (part)) * ATS)
#define FCW_O 222720
#define SMEM_BYTES 222976

__device__ __forceinline__ float fsig(float v) {
    return __fdividef(1.0f, 1.0f + __expf(-v));
}
__device__ __forceinline__ float ftanh(float v) {
    return __fdividef(2.0f, 1.0f + __expf(-2.0f * v)) - 1.0f;
}

__device__ __forceinline__ void mma16816(float d[4], const u32 a[4], u32 b0, u32 b1) {
    asm("mma.sync.aligned.m16n8k16.row.col.f32.f16.f16.f32 "
        "{%0,%1,%2,%3},{%4,%5,%6,%7},{%8,%9},{%0,%1,%2,%3};"
        : "+f"(d[0]), "+f"(d[1]), "+f"(d[2]), "+f"(d[3])
        : "r"(a[0]), "r"(a[1]), "r"(a[2]), "r"(a[3]), "r"(b0), "r"(b1));
}

__device__ __forceinline__ void sthalf2(char* bh, char* bl, int row, int col, float v) {
    __half hi = __float2half_rn(v);
    __half lo = __float2half_rn((v - __half2float(hi)) * 1024.0f);
    *(__half*)(bh + row * RS + col * 2) = hi;
    *(__half*)(bl + row * RS + col * 2) = lo;
}

template <int KS>
__device__ __forceinline__ void gemm_mma(
    const char* ah_b, const char* al_b, const char* wh_b, const char* wl_b,
    int n0A, int n0B, int g, int tq, float dm[2][4], float dc[2][4])
{
#pragma unroll
    for (int ks = 0; ks < KS; ++ks) {
        const int kb = ks * 32 + tq * 4;
        u32 ah[4], al[4];
        const char* p = ah_b + g * RS + kb;
        ah[0] = *(const u32*)(p);
        ah[1] = *(const u32*)(p + 8 * RS);
        ah[2] = *(const u32*)(p + 16);
        ah[3] = *(const u32*)(p + 8 * RS + 16);
        const char* q = al_b + g * RS + kb;
        al[0] = *(const u32*)(q);
        al[1] = *(const u32*)(q + 8 * RS);
        al[2] = *(const u32*)(q + 16);
        al[3] = *(const u32*)(q + 8 * RS + 16);
#pragma unroll
        for (int nn = 0; nn < 2; ++nn) {
            const int n0 = nn ? n0B : n0A;
            const char* pw = wh_b + (n0 + g) * RS + kb;
            u32 bh0 = *(const u32*)pw, bh1 = *(const u32*)(pw + 16);
            const char* ql = wl_b + (n0 + g) * RS + kb;
            u32 bl0 = *(const u32*)ql, bl1 = *(const u32*)(ql + 16);
            mma16816(dm[nn], ah, bh0, bh1);
            mma16816(dc[nn], al, bh0, bh1);
            mma16816(dc[nn], ah, bl0, bl1);
        }
    }
}

__device__ __forceinline__ void epi_act(
    float dm[2][4], float dc[2][4], int P, float sg, float mg, float bg,
    float c[2], float h[2])
{
    const float inv = 1.0f / 1024.0f;
#pragma unroll
    for (int nt = 0; nt < 2; ++nt) {
        float v0 = mg * fsig(sg * (dm[nt][0] + dc[nt][0] * inv)) - bg;
        float v1 = fsig(dm[nt][1] + dc[nt][1] * inv);
        float v2 = mg * fsig(sg * (dm[nt][2] + dc[nt][2] * inv)) - bg;
        float v3 = fsig(dm[nt][3] + dc[nt][3] * inv);
        float s0 = P ? v0 : v2, s1 = P ? v1 : v3;
        float r0 = __shfl_xor_sync(0xffffffffu, s0, 1);
        float r1 = __shfl_xor_sync(0xffffffffu, s1, 1);
        float iv = P ? r0 : v0, fv = P ? r1 : v1;
        float gv = P ? v2 : r0, ov = P ? v3 : r1;
        c[nt] = fv * c[nt] + iv * gv;
        h[nt] = ov * ftanh(c[nt]);
    }
}

extern __shared__ float smem_f[];

__global__ __launch_bounds__(NT, 1) void lstm2_fused_kernel(
    const float* __restrict__ x,
    const float* __restrict__ w_ih0, const float* __restrict__ w_hh0,
    const float* __restrict__ b_ih0, const float* __restrict__ b_hh0,
    const float* __restrict__ w_ih1, const float* __restrict__ w_hh1,
    const float* __restrict__ b_ih1, const float* __restrict__ b_hh1,
    const float* __restrict__ fc_w,  const float* __restrict__ fc_b,
    float* __restrict__ out)
{
    char* sb = (char*)smem_f;
    const int tid   = threadIdx.x;
    const int w     = tid >> 5;
    const int lane  = tid & 31;
    const int g     = lane >> 2;
    const int tq    = lane & 3;
    const int P     = tq & 1;
    const int uu    = tq >> 1;
    const int team  = (w >= 13);
    const int tw    = w - team * 13;
    const int ttid  = tid - team * 416;
    const int bbase = blockIdx.x * 32;

    for (int i = tid; i < SMEM_BYTES / 4; i += NT) ((u32*)sb)[i] = 0u;
    __syncthreads();

    // W rows 0-207: L2 gates. k<50 w_ih1 (h1), 51 bias1, 52-101 w_hh1 (h2).
    // W rows 208-415: L1 gates. k<50 w_hh0 (h1), 50 w_ih0 (x), 51 bias0.
    for (int idx = tid; idx < 416 * 102; idx += NT) {
        int n = idx / 102, k = idx - n * 102;
        float v = 0.0f;
        if (n < 208) {
            int r = (n & 3) * 50 + (n >> 2);
            if (k < 50)        v = w_ih1[r * 50 + k];
            else if (k == 51)  v = b_ih1[r] + b_hh1[r];
            else if (k >= 52)  v = w_hh1[r * 50 + (k - 52)];
        } else {
            int m = n - 208;
            int r = (m & 3) * 50 + (m >> 2);
            if (k < 50)        v = w_hh0[r * 50 + k];
            else if (k == 50)  v = w_ih0[r];
            else if (k == 51)  v = b_ih0[r] + b_hh0[r];
        }
        sthalf2(sb + W_H, sb + W_L, n, k, v);
    }
    for (int k = tid; k < 50; k += NT) ((float*)(sb + FCW_O))[k] = fc_w[k];
    __syncthreads();

    const float sg = P ? 2.0f : 1.0f;
    const float mg = P ? 2.0f : 1.0f;
    const float bg = P ? 1.0f : 0.0f;
    const int n0A = 8 * tw, n0B = 8 * (tw + 13);
    const int jA = 2 * tw + uu, jB = 2 * (tw + 13) + uu;
    const int brow = P ? g + 8 : g;

    float c1[2] = {0.f, 0.f}, c2[2] = {0.f, 0.f};
    float h1[2], h2[2];
    float dm[2][4], dc[2][4];

    // ---- prologue ----
    if (tid < 64) {  // bias col 51 = 1, all teams/bufs
        int tm = tid >> 5, buf = (tid >> 4) & 1, row = tid & 15;
        *(__half*)(sb + AT(tm, buf, 0) + row * RS + 51 * 2) = __float2half_rn(1.0f);
    }
    if (ttid < 16)   // x(1) into A[team,0] col 50
        sthalf2(sb + AT(team, 0, 0), sb + AT(team, 0, 1), ttid, 50,
                x[(bbase + team * 16 + ttid) * TLEN + 1]);
    {   // h1(0) scalar bootstrap for this thread's (j, brow)
        const float inv = 1.0f / 1024.0f;
        float x0 = x[(bbase + team * 16 + brow) * TLEN];
#pragma unroll
        for (int nt = 0; nt < 2; ++nt) {
            int j = nt ? jB : jA;
            if (j >= 50) continue;
            float pre[4];
#pragma unroll
            for (int ty = 0; ty < 4; ++ty) {
                const char* rp = sb + (208 + 4 * j + ty) * RS;
                float wv = __half2float(*(const __half*)(rp + W_H + 100)) +
                           __half2float(*(const __half*)(rp + W_L + 100)) * inv;
                float bv = __half2float(*(const __half*)(rp + W_H + 102)) +
                           __half2float(*(const __half*)(rp + W_L + 102)) * inv;
                pre[ty] = wv * x0 + bv;
            }
            float iv = fsig(pre[0]), fv = fsig(pre[1]);
            float gv = ftanh(pre[2]), ov = fsig(pre[3]);
            c1[nt] = iv * gv;
            float h = ov * ftanh(c1[nt]);
            sthalf2(sb + AT(team, 0, 0), sb + AT(team, 0, 1), brow, j, h);
        }
    }
    __syncthreads();

    // ---- main loop: one gemm phase + one barrier per step ----
    for (int s = 0; s < TLEN; ++s) {
        float xn = 0.0f;
        if (ttid < 16)
            xn = x[(bbase + team * 16 + ttid) * TLEN + ((s + 2 < TLEN) ? s + 2 : TLEN - 1)];
        const int cb = s & 1, nb = cb ^ 1;
        const char* ah = sb + AT(team, cb, 0);
        const char* al = sb + AT(team, cb, 1);
        char* wh = sb + AT(team, nb, 0);
        char* wl = sb + AT(team, nb, 1);

        // L2(s) gates
#pragma unroll
        for (int a = 0; a < 2; ++a)
#pragma unroll
            for (int r = 0; r < 4; ++r) { dm[a][r] = 0.f; dc[a][r] = 0.f; }
        gemm_mma<7>(ah, al, sb + W_H, sb + W_L, n0A, n0B, g, tq, dm, dc);
        epi_act(dm, dc, P, sg, mg, bg, c2, h2);
        if (jA < 50) sthalf2(wh, wl, brow, 52 + jA, h2[0]);
        if (jB < 50) sthalf2(wh, wl, brow, 52 + jB, h2[1]);

        // L1(s+1) gates (ks 0-3 only)
#pragma unroll
        for (int a = 0; a < 2; ++a)
#pragma unroll
            for (int r = 0; r < 4; ++r) { dm[a][r] = 0.f; dc[a][r] = 0.f; }
        gemm_mma<4>(ah, al, sb + W_H, sb + W_L, 208 + n0A, 208 + n0B, g, tq, dm, dc);
        epi_act(dm, dc, P, sg, mg, bg, c1, h1);
        if (jA < 50) sthalf2(wh, wl, brow, jA, h1[0]);
        if (jB < 50) sthalf2(wh, wl, brow, jB, h1[1]);

        if (ttid < 16) sthalf2(wh, wl, ttid, 50, xn);
        asm volatile("bar.sync %0, 416;" :: "r"(1 + team) : "memory");
    }

    // ---- final FC: h2(511) in A[team,0] cols 52-101 ----
    __syncthreads();
    if (tid < 32) {
        int tm = tid >> 4, row = tid & 15;
        const char* hh = sb + AT(tm, 0, 0);
        const char* hl = sb + AT(tm, 0, 1);
        const float* fcs = (const float*)(sb + FCW_O);
        float s = fc_b[0];
        const float inv = 1.0f / 1024.0f;
#pragma unroll 10
        for (int k = 0; k < 50; ++k) {
            float hi = __half2float(*(const __half*)(hh + row * RS + (52 + k) * 2));
            float lo = __half2float(*(const __half*)(hl + row * RS + (52 + k) * 2));
            s += (hi + lo * inv) * fcs[k];
        }
        out[bbase + tid] = s;
    }
}

extern "C" void kernel_launch(void* const* d_in, const int* in_sizes, int n_in,
                              void* d_out, int out_size) {
    const float* x     = (const float*)d_in[0];
    const float* w_ih0 = (const float*)d_in[1];
    const float* w_hh0 = (const float*)d_in[2];
    const float* b_ih0 = (const float*)d_in[3];
    const float* b_hh0 = (const float*)d_in[4];
    const float* w_ih1 = (const float*)d_in[5];
    const float* w_hh1 = (const float*)d_in[6];
    const float* b_ih1 = (const float*)d_in[7];
    const float* b_hh1 = (const float*)d_in[8];
    const float* fc_w  = (const float*)d_in[9];
    const float* fc_b  = (const float*)d_in[10];
    float* out = (float*)d_out;

    cudaFuncSetAttribute(lstm2_fused_kernel,
                         cudaFuncAttributeMaxDynamicSharedMemorySize,
                         SMEM_BYTES);

    lstm2_fused_kernel<<<128, NT, SMEM_BYTES>>>(
        x, w_ih0, w_hh0, b_ih0, b_hh0,
        w_ih1, w_hh1, b_ih1, b_hh1, fc_w, fc_b, out);
}

// round 17
// speedup vs baseline: 1.4645x; 1.4645x over previous
#include <cuda_runtime.h>
#include <cuda_fp16.h>
#include <cstdint>

// R16 = R15 fused single-GEMM-per-step with RS=240 (conflict-free stride).
// W[416 x K]: rows 0-207 L2 gates(t), rows 208-415 L1 gates(t+1).
// A[16 x K] = [h1(t) | x(t+1) | 1 | h2(t-1)]. One barrier/step.
// fp16 3-pass hi/lo (lo x1024). 2 teams x 13 warps.

typedef uint32_t u32;

#define NT 832
#define TLEN 512
#define RS 240
#define W_H 0
#define W_L 99840
#define A_O 199680
#define ATS 3840
#define AT(tm, buf, part) (A_O + (((tm) * 2 + (buf)) * 2 + (part)) * ATS)
#define FCW_O 230400
#define SMEM_BYTES 230656

__device__ __forceinline__ float fsig(float v) {
    return __fdividef(1.0f, 1.0f + __expf(-v));
}
__device__ __forceinline__ float ftanh(float v) {
    return __fdividef(2.0f, 1.0f + __expf(-2.0f * v)) - 1.0f;
}

__device__ __forceinline__ void mma16816(float d[4], const u32 a[4], u32 b0, u32 b1) {
    asm("mma.sync.aligned.m16n8k16.row.col.f32.f16.f16.f32 "
        "{%0,%1,%2,%3},{%4,%5,%6,%7},{%8,%9},{%0,%1,%2,%3};"
        : "+f"(d[0]), "+f"(d[1]), "+f"(d[2]), "+f"(d[3])
        : "r"(a[0]), "r"(a[1]), "r"(a[2]), "r"(a[3]), "r"(b0), "r"(b1));
}

__device__ __forceinline__ void sthalf2(char* bh, char* bl, int row, int col, float v) {
    __half hi = __float2half_rn(v);
    __half lo = __float2half_rn((v - __half2float(hi)) * 1024.0f);
    *(__half*)(bh + row * RS + col * 2) = hi;
    *(__half*)(bl + row * RS + col * 2) = lo;
}

template <int KS>
__device__ __forceinline__ void gemm_mma(
    const char* ah_b, const char* al_b, const char* wh_b, const char* wl_b,
    int n0A, int n0B, int g, int tq, float dm[2][4], float dc[2][4])
{
#pragma unroll
    for (int ks = 0; ks < KS; ++ks) {
        const int kb = ks * 32 + tq * 4;
        u32 ah[4], al[4];
        const char* p = ah_b + g * RS + kb;
        ah[0] = *(const u32*)(p);
        ah[1] = *(const u32*)(p + 8 * RS);
        ah[2] = *(const u32*)(p + 16);
        ah[3] = *(const u32*)(p + 8 * RS + 16);
        const char* q = al_b + g * RS + kb;
        al[0] = *(const u32*)(q);
        al[1] = *(const u32*)(q + 8 * RS);
        al[2] = *(const u32*)(q + 16);
        al[3] = *(const u32*)(q + 8 * RS + 16);
#pragma unroll
        for (int nn = 0; nn < 2; ++nn) {
            const int n0 = nn ? n0B : n0A;
            const char* pw = wh_b + (n0 + g) * RS + kb;
            u32 bh0 = *(const u32*)pw, bh1 = *(const u32*)(pw + 16);
            const char* ql = wl_b + (n0 + g) * RS + kb;
            u32 bl0 = *(const u32*)ql, bl1 = *(const u32*)(ql + 16);
            mma16816(dm[nn], ah, bh0, bh1);
            mma16816(dc[nn], al, bh0, bh1);
            mma16816(dc[nn], ah, bl0, bl1);
        }
    }
}

__device__ __forceinline__ void epi_act(
    float dm[2][4], float dc[2][4], int P, float sg, float mg, float bg,
    float c[2], float h[2])
{
    const float inv = 1.0f / 1024.0f;
#pragma unroll
    for (int nt = 0; nt < 2; ++nt) {
        float v0 = mg * fsig(sg * (dm[nt][0] + dc[nt][0] * inv)) - bg;
        float v1 = fsig(dm[nt][1] + dc[nt][1] * inv);
        float v2 = mg * fsig(sg * (dm[nt][2] + dc[nt][2] * inv)) - bg;
        float v3 = fsig(dm[nt][3] + dc[nt][3] * inv);
        float s0 = P ? v0 : v2, s1 = P ? v1 : v3;
        float r0 = __shfl_xor_sync(0xffffffffu, s0, 1);
        float r1 = __shfl_xor_sync(0xffffffffu, s1, 1);
        float iv = P ? r0 : v0, fv = P ? r1 : v1;
        float gv = P ? v2 : r0, ov = P ? v3 : r1;
        c[nt] = fv * c[nt] + iv * gv;
        h[nt] = ov * ftanh(c[nt]);
    }
}

extern __shared__ float smem_f[];

__global__ __launch_bounds__(NT, 1) void lstm2_fused_kernel(
    const float* __restrict__ x,
    const float* __restrict__ w_ih0, const float* __restrict__ w_hh0,
    const float* __restrict__ b_ih0, const float* __restrict__ b_hh0,
    const float* __restrict__ w_ih1, const float* __restrict__ w_hh1,
    const float* __restrict__ b_ih1, const float* __restrict__ b_hh1,
    const float* __restrict__ fc_w,  const float* __restrict__ fc_b,
    float* __restrict__ out)
{
    char* sb = (char*)smem_f;
    const int tid   = threadIdx.x;
    const int w     = tid >> 5;
    const int lane  = tid & 31;
    const int g     = lane >> 2;
    const int tq    = lane & 3;
    const int P     = tq & 1;
    const int uu    = tq >> 1;
    const int team  = (w >= 13);
    const int tw    = w - team * 13;
    const int ttid  = tid - team * 416;
    const int bbase = blockIdx.x * 32;

    for (int i = tid; i < SMEM_BYTES / 4; i += NT) ((u32*)sb)[i] = 0u;
    __syncthreads();

    // W rows 0-207: L2 gates. k<50 w_ih1 (h1), 51 bias1, 52-101 w_hh1 (h2).
    // W rows 208-415: L1 gates. k<50 w_hh0 (h1), 50 w_ih0 (x), 51 bias0.
    for (int idx = tid; idx < 416 * 102; idx += NT) {
        int n = idx / 102, k = idx - n * 102;
        float v = 0.0f;
        if (n < 208) {
            int r = (n & 3) * 50 + (n >> 2);
            if (k < 50)        v = w_ih1[r * 50 + k];
            else if (k == 51)  v = b_ih1[r] + b_hh1[r];
            else if (k >= 52)  v = w_hh1[r * 50 + (k - 52)];
        } else {
            int m = n - 208;
            int r = (m & 3) * 50 + (m >> 2);
            if (k < 50)        v = w_hh0[r * 50 + k];
            else if (k == 50)  v = w_ih0[r];
            else if (k == 51)  v = b_ih0[r] + b_hh0[r];
        }
        sthalf2(sb + W_H, sb + W_L, n, k, v);
    }
    for (int k = tid; k < 50; k += NT) ((float*)(sb + FCW_O))[k] = fc_w[k];
    __syncthreads();

    const float sg = P ? 2.0f : 1.0f;
    const float mg = P ? 2.0f : 1.0f;
    const float bg = P ? 1.0f : 0.0f;
    const int n0A = 8 * tw, n0B = 8 * (tw + 13);
    const int jA = 2 * tw + uu, jB = 2 * (tw + 13) + uu;
    const int brow = P ? g + 8 : g;

    float c1[2] = {0.f, 0.f}, c2[2] = {0.f, 0.f};
    float h1[2], h2[2];
    float dm[2][4], dc[2][4];

    // ---- prologue ----
    if (tid < 64) {  // bias col 51 = 1, all teams/bufs
        int tm = tid >> 5, buf = (tid >> 4) & 1, row = tid & 15;
        *(__half*)(sb + AT(tm, buf, 0) + row * RS + 51 * 2) = __float2half_rn(1.0f);
    }
    if (ttid < 16)   // x(1) into A[team,0] col 50
        sthalf2(sb + AT(team, 0, 0), sb + AT(team, 0, 1), ttid, 50,
                x[(bbase + team * 16 + ttid) * TLEN + 1]);
    {   // h1(0) scalar bootstrap
        const float inv = 1.0f / 1024.0f;
        float x0 = x[(bbase + team * 16 + brow) * TLEN];
#pragma unroll
        for (int nt = 0; nt < 2; ++nt) {
            int j = nt ? jB : jA;
            if (j >= 50) continue;
            float pre[4];
#pragma unroll
            for (int ty = 0; ty < 4; ++ty) {
                const char* rp = sb + (208 + 4 * j + ty) * RS;
                float wv = __half2float(*(const __half*)(rp + W_H + 100)) +
                           __half2float(*(const __half*)(rp + W_L + 100)) * inv;
                float bv = __half2float(*(const __half*)(rp + W_H + 102)) +
                           __half2float(*(const __half*)(rp + W_L + 102)) * inv;
                pre[ty] = wv * x0 + bv;
            }
            float iv = fsig(pre[0]), fv = fsig(pre[1]);
            float gv = ftanh(pre[2]), ov = fsig(pre[3]);
            c1[nt] = iv * gv;
            float h = ov * ftanh(c1[nt]);
            sthalf2(sb + AT(team, 0, 0), sb + AT(team, 0, 1), brow, j, h);
        }
    }
    __syncthreads();

    // ---- main loop: one gemm phase + one barrier per step ----
    for (int s = 0; s < TLEN; ++s) {
        float xn = 0.0f;
        if (ttid < 16)
            xn = x[(bbase + team * 16 + ttid) * TLEN + ((s + 2 < TLEN) ? s + 2 : TLEN - 1)];
        const int cb = s & 1, nb = cb ^ 1;
        const char* ah = sb + AT(team, cb, 0);
        const char* al = sb + AT(team, cb, 1);
        char* wh = sb + AT(team, nb, 0);
        char* wl = sb + AT(team, nb, 1);

        // L2(s) gates
#pragma unroll
        for (int a = 0; a < 2; ++a)
#pragma unroll
            for (int r = 0; r < 4; ++r) { dm[a][r] = 0.f; dc[a][r] = 0.f; }
        gemm_mma<7>(ah, al, sb + W_H, sb + W_L, n0A, n0B, g, tq, dm, dc);
        epi_act(dm, dc, P, sg, mg, bg, c2, h2);
        if (jA < 50) sthalf2(wh, wl, brow, 52 + jA, h2[0]);
        if (jB < 50) sthalf2(wh, wl, brow, 52 + jB, h2[1]);

        // L1(s+1) gates (ks 0-3 only)
#pragma unroll
        for (int a = 0; a < 2; ++a)
#pragma unroll
            for (int r = 0; r < 4; ++r) { dm[a][r] = 0.f; dc[a][r] = 0.f; }
        gemm_mma<4>(ah, al, sb + W_H, sb + W_L, 208 + n0A, 208 + n0B, g, tq, dm, dc);
        epi_act(dm, dc, P, sg, mg, bg, c1, h1);
        if (jA < 50) sthalf2(wh, wl, brow, jA, h1[0]);
        if (jB < 50) sthalf2(wh, wl, brow, jB, h1[1]);

        if (ttid < 16) sthalf2(wh, wl, ttid, 50, xn);
        asm volatile("bar.sync %0, 416;" :: "r"(1 + team) : "memory");
    }

    // ---- final FC: h2(511) in A[team,0] cols 52-101 ----
    __syncthreads();
    if (tid < 32) {
        int tm = tid >> 4, row = tid & 15;
        const char* hh = sb + AT(tm, 0, 0);
        const char* hl = sb + AT(tm, 0, 1);
        const float* fcs = (const float*)(sb + FCW_O);
        float s = fc_b[0];
        const float inv = 1.0f / 1024.0f;
#pragma unroll 10
        for (int k = 0; k < 50; ++k) {
            float hi = __half2float(*(const __half*)(hh + row * RS + (52 + k) * 2));
            float lo = __half2float(*(const __half*)(hl + row * RS + (52 + k) * 2));
            s += (hi + lo * inv) * fcs[k];
        }
        out[bbase + tid] = s;
    }
}

extern "C" void kernel_launch(void* const* d_in, const int* in_sizes, int n_in,
                              void* d_out, int out_size) {
    const float* x     = (const float*)d_in[0];
    const float* w_ih0 = (const float*)d_in[1];
    const float* w_hh0 = (const float*)d_in[2];
    const float* b_ih0 = (const float*)d_in[3];
    const float* b_hh0 = (const float*)d_in[4];
    const float* w_ih1 = (const float*)d_in[5];
    const float* w_hh1 = (const float*)d_in[6];
    const float* b_ih1 = (const float*)d_in[7];
    const float* b_hh1 = (const float*)d_in[8];
    const float* fc_w  = (const float*)d_in[9];
    const float* fc_b  = (const float*)d_in[10];
    float* out = (float*)d_out;

    cudaFuncSetAttribute(lstm2_fused_kernel,
                         cudaFuncAttributeMaxDynamicSharedMemorySize,
                         SMEM_BYTES);

    lstm2_fused_kernel<<<128, NT, SMEM_BYTES>>>(
        x, w_ih0, w_hh0, b_ih0, b_hh0,
        w_ih1, w_hh1, b_ih1, b_hh1, fc_w, fc_b, out);
}